// round 3
// baseline (speedup 1.0000x reference)
#include <cuda_runtime.h>
#include <cstdint>
#include <cstddef>

// ---------------------------------------------------------------------------
// HighwayLayerDiscrete — persistent fp32 kernel.
// y_{t} = y_{t-1} + Wout^T·lrelu(...)(highway), 256 steps × 4 GEMM layers,
// M=64, N=1024, K=1024(/512). 128 CTAs (1/SM), each owns an 8-column slice
// of every weight matrix cached in SMEM for the full run. Activations are
// exchanged through L2 in TRANSPOSED layout (actT[u][r]) so staging is a
// straight coalesced copy. Grid barrier = release/acquire epoch flags.
// ---------------------------------------------------------------------------

#define NCTA     128
#define NTHREADS 256
#define UNITS    1024
#define EMBED    512
#define BATCH    64
#define SEQ      256
#define ALPHA    0.2f

// ---- shared memory layout (float offsets) ----
#define OFF_WY   0                 // 1024 x 8
#define OFF_WH0  8192
#define OFF_WH1  16384
#define OFF_WO   24576
#define OFF_WX   32768             // 512 x 8
#define OFF_AT   36864             // double-buffered 64k x 64r  (2 x 4096)
#define OFF_RED  45056             // 8 warps x (64 rows x 9)
#define OFF_BIN  49664
#define OFF_BH0  49672
#define OFF_BH1  49680
#define OFF_BO   49688
#define SMEM_FLOATS 49696
#define SMEM_BYTES  (SMEM_FLOATS * 4)   // 198784 B < 227 KB

// ---- global state (static, no allocation) ----
__device__ float    g_yT [UNITS * BATCH];     // y transposed [u][r]
__device__ float    g_hAT[UNITS * BATCH];
__device__ float    g_hBT[UNITS * BATCH];
__device__ float    g_xeT[2][EMBED * BATCH];  // gathered embeddings, transposed
__device__ unsigned g_flags[NCTA * 32];       // 128B-spaced epoch flags

// ---- memory-model helpers ----
__device__ __forceinline__ unsigned ld_acq(const unsigned* p) {
    unsigned v;
    asm volatile("ld.acquire.gpu.global.u32 %0, [%1];" : "=r"(v) : "l"(p) : "memory");
    return v;
}
__device__ __forceinline__ void st_rel(unsigned* p, unsigned v) {
    asm volatile("st.release.gpu.global.u32 [%0], %1;" :: "l"(p), "r"(v) : "memory");
}

// Grid barrier. All 128 CTAs are co-resident (1 CTA/SM, 128 <= 148 SMs).
__device__ __forceinline__ void gbar(int cta, int tid, unsigned e) {
    __syncthreads();
    if (tid == 0) st_rel(&g_flags[cta * 32], e);
    if (tid < NCTA) {
        while (ld_acq(&g_flags[tid * 32]) < e) { }
    }
    __syncthreads();
}

// Gather embedding rows for timestep t into transposed buffer.
// CTA c owns k in [c*4, c*4+4). Threads 0..63 handle one batch row each.
__device__ __forceinline__ void build_xeT(int cta, int tid, int buf, int t,
                                          const int* x, const float* emb) {
    if (tid < BATCH) {
        int r   = tid;
        int idx = __ldg(&x[r * SEQ + t]);
        float4 v = __ldg((const float4*)&emb[(size_t)idx * EMBED + cta * 4]);
        float* dst = g_xeT[buf];
        int k0 = cta * 4;
        __stcg(&dst[(k0 + 0) * BATCH + r], v.x);
        __stcg(&dst[(k0 + 1) * BATCH + r], v.y);
        __stcg(&dst[(k0 + 2) * BATCH + r], v.z);
        __stcg(&dst[(k0 + 3) * BATCH + r], v.w);
    }
}

// One GEMM pass: acc[8][2] += srcT(64 x K_chunked) * Wsmem(K x 8-col slice).
// Software pipelined: next 16KB chunk prefetched into registers during FFMA,
// double-buffered in SMEM. Thread (w=warp k-slice, tr row-group, tc col-pair).
__device__ __forceinline__ void gemm_pass(float* sm, const float* srcT, int wOff,
                                          int nchunk, float acc[8][2],
                                          int w, int tr, int tc) {
    const int tid = threadIdx.x;
    float4 r[4];
    // preload chunk 0
    {
        const float4* src = (const float4*)srcT;
        #pragma unroll
        for (int j = 0; j < 4; j++) r[j] = __ldcg(src + tid + j * NTHREADS);
        float4* dst = (float4*)(sm + OFF_AT);
        #pragma unroll
        for (int j = 0; j < 4; j++) dst[tid + j * NTHREADS] = r[j];
    }
    __syncthreads();

    for (int kb = 0; kb < nchunk; kb++) {
        if (kb + 1 < nchunk) {          // prefetch next chunk (L2) during FFMA
            const float4* src = (const float4*)(srcT + (kb + 1) * (64 * BATCH));
            #pragma unroll
            for (int j = 0; j < 4; j++) r[j] = __ldcg(src + tid + j * NTHREADS);
        }
        const float* At = sm + OFF_AT + (kb & 1) * 4096;
        const float* W  = sm + wOff + kb * 64 * 8;
        #pragma unroll
        for (int kk = 0; kk < 8; kk++) {
            int k = w * 8 + kk;
            const float* ar = At + k * 64 + tr * 8;
            float4 a0 = *(const float4*)(ar);
            float4 a1 = *(const float4*)(ar + 4);
            float2 wv = *(const float2*)(W + k * 8 + tc * 2);
            acc[0][0] = fmaf(a0.x, wv.x, acc[0][0]); acc[0][1] = fmaf(a0.x, wv.y, acc[0][1]);
            acc[1][0] = fmaf(a0.y, wv.x, acc[1][0]); acc[1][1] = fmaf(a0.y, wv.y, acc[1][1]);
            acc[2][0] = fmaf(a0.z, wv.x, acc[2][0]); acc[2][1] = fmaf(a0.z, wv.y, acc[2][1]);
            acc[3][0] = fmaf(a0.w, wv.x, acc[3][0]); acc[3][1] = fmaf(a0.w, wv.y, acc[3][1]);
            acc[4][0] = fmaf(a1.x, wv.x, acc[4][0]); acc[4][1] = fmaf(a1.x, wv.y, acc[4][1]);
            acc[5][0] = fmaf(a1.y, wv.x, acc[5][0]); acc[5][1] = fmaf(a1.y, wv.y, acc[5][1]);
            acc[6][0] = fmaf(a1.z, wv.x, acc[6][0]); acc[6][1] = fmaf(a1.z, wv.y, acc[6][1]);
            acc[7][0] = fmaf(a1.w, wv.x, acc[7][0]); acc[7][1] = fmaf(a1.w, wv.y, acc[7][1]);
        }
        if (kb + 1 < nchunk) {
            __syncthreads();
            float4* dst = (float4*)(sm + OFF_AT + ((kb + 1) & 1) * 4096);
            #pragma unroll
            for (int j = 0; j < 4; j++) dst[tid + j * NTHREADS] = r[j];
            __syncthreads();
        }
    }
}

// Cross-warp reduction (8 k-slice partials) + bias + activation + store.
// MODE 0: lrelu -> dstT.  MODE 1: residual: y += val; store y_T and out.
template<int MODE>
__device__ __forceinline__ void reduce_epi(float* sm, float acc[8][2],
                                           float* dstT, float* outp,
                                           int biasOff, int ctabase, int t) {
    const int tid = threadIdx.x;
    const int w = tid >> 5, lane = tid & 31;
    const int tr = lane >> 2, tc = lane & 3;
    float* red = sm + OFF_RED + w * 576;
    #pragma unroll
    for (int rr = 0; rr < 8; rr++) {
        int row = tr * 8 + rr;
        red[row * 9 + tc * 2]     = acc[rr][0];
        red[row * 9 + tc * 2 + 1] = acc[rr][1];
    }
    __syncthreads();
    int oid = tid * 2;
    int row = oid >> 3, col = oid & 7;
    float s0 = sm[biasOff + col];
    float s1 = sm[biasOff + col + 1];
    #pragma unroll
    for (int ww = 0; ww < 8; ww++) {
        s0 += sm[OFF_RED + ww * 576 + row * 9 + col];
        s1 += sm[OFF_RED + ww * 576 + row * 9 + col + 1];
    }
    int u0 = ctabase + col;
    if (MODE == 0) {
        s0 = s0 > 0.f ? s0 : ALPHA * s0;
        s1 = s1 > 0.f ? s1 : ALPHA * s1;
        __stcg(&dstT[u0 * BATCH + row], s0);
        __stcg(&dstT[(u0 + 1) * BATCH + row], s1);
    } else {
        float y0 = __ldcg(&dstT[u0 * BATCH + row]) + s0;        // own columns
        float y1 = __ldcg(&dstT[(u0 + 1) * BATCH + row]) + s1;
        __stcg(&dstT[u0 * BATCH + row], y0);
        __stcg(&dstT[(u0 + 1) * BATCH + row], y1);
        size_t ob = (size_t)row * SEQ * UNITS + (size_t)t * UNITS + u0;
        __stcg(&outp[ob], y0);
        __stcg(&outp[ob + 1], y1);
    }
    __syncthreads();
}

// ---- prologue: reset barrier flags, init y from broadcast h0 ----
__global__ void hw_init(const float* __restrict__ h0) {
    int id = blockIdx.x * blockDim.x + threadIdx.x;   // 32768 threads
    if (blockIdx.x == 0 && threadIdx.x < NCTA) __stcg(&g_flags[threadIdx.x * 32], 0u);
    #pragma unroll
    for (int j = 0; j < 2; j++) {
        int i = id + j * 32768;                       // i = u*64 + r
        __stcg(&g_yT[i], __ldg(&h0[i >> 6]));
    }
}

// ---- main persistent kernel ----
__global__ void __launch_bounds__(NTHREADS, 1)
hw_main(const int* __restrict__ x, const float* __restrict__ emb,
        const float* __restrict__ wy, const float* __restrict__ wx,
        const float* __restrict__ bin, const float* __restrict__ wh,
        const float* __restrict__ bh, const float* __restrict__ wo,
        const float* __restrict__ bo, float* __restrict__ out) {
    extern __shared__ float sm[];
    const int cta = blockIdx.x, tid = threadIdx.x;
    const int ctabase = cta * 8;
    const int w = tid >> 5, lane = tid & 31;
    const int tr = lane >> 2, tc = lane & 3;

    // --- load this CTA's 8-column weight slices into SMEM (one-time) ---
    for (int i = tid; i < 2048; i += NTHREADS) {      // 1024 k x 2 halves
        int k = i >> 1, h = (i & 1) << 2;
        *(float4*)&sm[OFF_WY  + k * 8 + h] = __ldg((const float4*)&wy[(size_t)k * UNITS + ctabase + h]);
        *(float4*)&sm[OFF_WH0 + k * 8 + h] = __ldg((const float4*)&wh[(size_t)k * UNITS + ctabase + h]);
        *(float4*)&sm[OFF_WH1 + k * 8 + h] = __ldg((const float4*)&wh[(size_t)(UNITS * UNITS) + (size_t)k * UNITS + ctabase + h]);
        *(float4*)&sm[OFF_WO  + k * 8 + h] = __ldg((const float4*)&wo[(size_t)k * UNITS + ctabase + h]);
    }
    for (int i = tid; i < 1024; i += NTHREADS) {      // 512 k x 2 halves
        int k = i >> 1, h = (i & 1) << 2;
        *(float4*)&sm[OFF_WX + k * 8 + h] = __ldg((const float4*)&wx[(size_t)k * UNITS + ctabase + h]);
    }
    if (tid < 8) {
        sm[OFF_BIN + tid] = __ldg(&bin[ctabase + tid]);
        sm[OFF_BH0 + tid] = __ldg(&bh[ctabase + tid]);
        sm[OFF_BH1 + tid] = __ldg(&bh[UNITS + ctabase + tid]);
        sm[OFF_BO  + tid] = __ldg(&bo[ctabase + tid]);
    }
    __syncthreads();

    unsigned e = 0;
    build_xeT(cta, tid, 0, 0, x, emb);                // embeddings for t=0
    gbar(cta, tid, ++e);

    for (int t = 0; t < SEQ; t++) {
        float acc[8][2];

        // ---- layer 0: lrelu(y*Wy + xe*Wx + b_in) -> hA ----
        #pragma unroll
        for (int i = 0; i < 8; i++) { acc[i][0] = 0.f; acc[i][1] = 0.f; }
        gemm_pass(sm, g_yT, OFF_WY, 16, acc, w, tr, tc);
        gemm_pass(sm, g_xeT[t & 1], OFF_WX, 8, acc, w, tr, tc);
        reduce_epi<0>(sm, acc, g_hAT, nullptr, OFF_BIN, ctabase, t);
        gbar(cta, tid, ++e);

        if (t + 1 < SEQ) build_xeT(cta, tid, (t + 1) & 1, t + 1, x, emb);

        // ---- layer 1 ----
        #pragma unroll
        for (int i = 0; i < 8; i++) { acc[i][0] = 0.f; acc[i][1] = 0.f; }
        gemm_pass(sm, g_hAT, OFF_WH0, 16, acc, w, tr, tc);
        reduce_epi<0>(sm, acc, g_hBT, nullptr, OFF_BH0, ctabase, t);
        gbar(cta, tid, ++e);

        // ---- layer 2 ----
        #pragma unroll
        for (int i = 0; i < 8; i++) { acc[i][0] = 0.f; acc[i][1] = 0.f; }
        gemm_pass(sm, g_hBT, OFF_WH1, 16, acc, w, tr, tc);
        reduce_epi<0>(sm, acc, g_hAT, nullptr, OFF_BH1, ctabase, t);
        gbar(cta, tid, ++e);

        // ---- layer 3: y += h*Wout + b_out ; write out[:, t, :] ----
        #pragma unroll
        for (int i = 0; i < 8; i++) { acc[i][0] = 0.f; acc[i][1] = 0.f; }
        gemm_pass(sm, g_hAT, OFF_WO, 16, acc, w, tr, tc);
        reduce_epi<1>(sm, acc, g_yT, out, OFF_BO, ctabase, t);
        gbar(cta, tid, ++e);
    }
}

extern "C" void kernel_launch(void* const* d_in, const int* in_sizes, int n_in,
                              void* d_out, int out_size) {
    const int*   x    = (const int*)  d_in[0];
    const float* emb  = (const float*)d_in[1];
    const float* wy   = (const float*)d_in[2];
    const float* wx   = (const float*)d_in[3];
    const float* bin  = (const float*)d_in[4];
    const float* wh   = (const float*)d_in[5];
    const float* bh   = (const float*)d_in[6];
    const float* wo   = (const float*)d_in[7];
    const float* bo   = (const float*)d_in[8];
    const float* h0   = (const float*)d_in[9];
    float* out = (float*)d_out;

    cudaFuncSetAttribute(hw_main, cudaFuncAttributeMaxDynamicSharedMemorySize, SMEM_BYTES);

    hw_init<<<NCTA, NTHREADS>>>(h0);
    hw_main<<<NCTA, NTHREADS, SMEM_BYTES>>>(x, emb, wy, wx, bin, wh, bh, wo, bo, out);
}

// round 4
// speedup vs baseline: 1.1464x; 1.1464x over previous
#include <cuda_runtime.h>
#include <cstdint>
#include <cstddef>

// ---------------------------------------------------------------------------
// HighwayLayerDiscrete — persistent fp32 kernel, v3.
// 128 CTAs (1/SM), 512 threads. Each CTA owns an 8-column slice of every
// weight matrix in SMEM. Activations are read DIRECTLY from L2 (__ldcg,
// coalesced LDG.128, register-pipelined) — no SMEM staging, no per-chunk
// syncs. Lane tiling: (ks, rg) = 2 k-values x 16 row-groups; thread computes
// 4 rows x 8 cols for its k; ks halves merged with shfl.bfly(16).
// Grid barrier = release/acquire epoch flags (all CTAs co-resident).
// ---------------------------------------------------------------------------

#define NCTA     128
#define NTHREADS 512
#define UNITS    1024
#define EMBED    512
#define BATCH    64
#define SEQ      256
#define ALPHA    0.2f

// ---- shared memory layout (float offsets) ----
#define OFF_WY   0           // 1024 x 8
#define OFF_WH0  8192
#define OFF_WH1  16384
#define OFF_WO   24576
#define OFF_WX   32768       // 512 x 8
#define OFF_RED  36864       // 16 warps x (64 rows x 9)
#define OFF_B    46080       // biases: [0..7]=bin [8..15]=bh0 [16..23]=bh1 [24..31]=bo
#define SMEM_FLOATS 46112
#define SMEM_BYTES  (SMEM_FLOATS * 4)   // 184448 B

// ---- global state (static, no allocation) ----
__device__ float    g_yT [UNITS * BATCH];     // transposed [u][r]
__device__ float    g_hAT[UNITS * BATCH];
__device__ float    g_hBT[UNITS * BATCH];
__device__ float    g_xeT[2][EMBED * BATCH];
__device__ unsigned g_flags[NCTA * 32];       // 128B-spaced epoch flags

// ---- memory-model helpers ----
__device__ __forceinline__ unsigned ld_acq(const unsigned* p) {
    unsigned v;
    asm volatile("ld.acquire.gpu.global.u32 %0, [%1];" : "=r"(v) : "l"(p) : "memory");
    return v;
}
__device__ __forceinline__ void st_rel(unsigned* p, unsigned v) {
    asm volatile("st.release.gpu.global.u32 [%0], %1;" :: "l"(p), "r"(v) : "memory");
}

// Grid barrier. All 128 CTAs co-resident (1 CTA/SM, 128 <= 148 SMs).
__device__ __forceinline__ void gbar(int cta, int tid, unsigned e) {
    __syncthreads();
    if (tid == 0) st_rel(&g_flags[cta * 32], e);
    if (tid < NCTA) {
        while (ld_acq(&g_flags[tid * 32]) < e) { }
    }
    __syncthreads();
}

// Gather embedding rows for timestep t into transposed buffer.
// CTA c owns k in [c*4, c*4+4). Threads 0..63: one batch row each.
__device__ __forceinline__ void build_xeT(int cta, int tid, int buf, int t,
                                          const int* x, const float* emb) {
    if (tid < BATCH) {
        int r   = tid;
        int idx = __ldg(&x[r * SEQ + t]);
        float4 v = __ldg((const float4*)&emb[(size_t)idx * EMBED + cta * 4]);
        float* dst = g_xeT[buf];
        int k0 = cta * 4;
        __stcg(&dst[(k0 + 0) * BATCH + r], v.x);
        __stcg(&dst[(k0 + 1) * BATCH + r], v.y);
        __stcg(&dst[(k0 + 2) * BATCH + r], v.z);
        __stcg(&dst[(k0 + 3) * BATCH + r], v.w);
    }
}

#define FFMA_ROW(i, av)                                            \
    acc[i][0] = fmaf(av, w0.x, acc[i][0]);                         \
    acc[i][1] = fmaf(av, w0.y, acc[i][1]);                         \
    acc[i][2] = fmaf(av, w0.z, acc[i][2]);                         \
    acc[i][3] = fmaf(av, w0.w, acc[i][3]);                         \
    acc[i][4] = fmaf(av, w1.x, acc[i][4]);                         \
    acc[i][5] = fmaf(av, w1.y, acc[i][5]);                         \
    acc[i][6] = fmaf(av, w1.z, acc[i][6]);                         \
    acc[i][7] = fmaf(av, w1.w, acc[i][7]);

// acc[4][8] += srcT(64r x nk) * Wsmem(nk x 8 cols).
// Warp w owns k in [w*nk/16, (w+1)*nk/16). Lane (ks, rg) handles k = base+2j+ks,
// rows rg*4..rg*4+3, all 8 cols. Acts streamed from L2 with 4-deep reg pipeline.
__device__ __forceinline__ void gemm_pass(const float* sm, const float* __restrict__ srcT,
                                          int wOff, int nk, float acc[4][8],
                                          int w, int ks, int rg) {
    const int nkw   = nk >> 4;          // k per warp
    const int np    = nkw >> 1;         // pairs per warp (16 or 32)
    const int kbase = w * nkw + ks;
    const float4* src = (const float4*)srcT;

    float4 ab[4];
    #pragma unroll
    for (int j = 0; j < 4; j++)
        ab[j] = __ldcg(src + (kbase + 2 * j) * 16 + rg);

    #pragma unroll 4
    for (int j = 0; j < np; j++) {
        float4 a = ab[j & 3];
        if (j + 4 < np)
            ab[j & 3] = __ldcg(src + (kbase + 2 * (j + 4)) * 16 + rg);
        int k = kbase + 2 * j;
        float4 w0 = *(const float4*)(sm + wOff + k * 8);
        float4 w1 = *(const float4*)(sm + wOff + k * 8 + 4);
        FFMA_ROW(0, a.x)
        FFMA_ROW(1, a.y)
        FFMA_ROW(2, a.z)
        FFMA_ROW(3, a.w)
    }
}

// ks-combine (shfl.bfly 16) + 16-warp smem reduction + bias + activation.
// MODE 0: lrelu -> dstT.  MODE 1: y += val, store yT and out[:,t,:].
template<int MODE>
__device__ __forceinline__ void reduce_epi(float* sm, float acc[4][8],
                                           float* dstT, float* outp,
                                           int biasOff, int ctabase, int t,
                                           int w, int ks, int rg) {
    const int tid = threadIdx.x;
    #pragma unroll
    for (int i = 0; i < 4; i++)
        #pragma unroll
        for (int c = 0; c < 8; c++)
            acc[i][c] += __shfl_xor_sync(0xffffffffu, acc[i][c], 16);

    // Both halves hold sums: ks=0 stores rows rg*4+{0,1}, ks=1 stores +{2,3}.
    float* red = sm + OFF_RED + w * 576;
    int r0 = ks * 2;
    #pragma unroll
    for (int i = 0; i < 2; i++) {
        int row = rg * 4 + r0 + i;
        #pragma unroll
        for (int c = 0; c < 8; c++) red[row * 9 + c] = acc[r0 + i][c];
    }
    __syncthreads();

    int c = tid >> 6, r = tid & 63;           // coalesced in r for dstT
    float s = sm[biasOff + c];
    #pragma unroll
    for (int ww = 0; ww < 16; ww++) s += sm[OFF_RED + ww * 576 + r * 9 + c];

    int u = ctabase + c;
    if (MODE == 0) {
        s = s > 0.f ? s : ALPHA * s;
        __stcg(&dstT[u * BATCH + r], s);
    } else {
        float y = __ldcg(&dstT[u * BATCH + r]) + s;
        __stcg(&dstT[u * BATCH + r], y);
        // restage through smem for a units-coalesced out write
        __syncthreads();
        sm[OFF_RED + r * 9 + c] = y;
        __syncthreads();
        int b = tid >> 3, cc = tid & 7;
        __stcg(&outp[(size_t)b * (SEQ * UNITS) + (size_t)t * UNITS + ctabase + cc],
               sm[OFF_RED + b * 9 + cc]);
    }
}

// ---- prologue: reset barrier flags, init y from broadcast h0 ----
__global__ void hw_init(const float* __restrict__ h0) {
    int id = blockIdx.x * blockDim.x + threadIdx.x;   // 32768 threads
    if (blockIdx.x == 0 && threadIdx.x < NCTA) __stcg(&g_flags[threadIdx.x * 32], 0u);
    #pragma unroll
    for (int j = 0; j < 2; j++) {
        int i = id + j * 32768;                       // i = u*64 + r
        __stcg(&g_yT[i], __ldg(&h0[i >> 6]));
    }
}

// ---- main persistent kernel ----
__global__ void __launch_bounds__(NTHREADS, 1)
hw_main(const int* __restrict__ x, const float* __restrict__ emb,
        const float* __restrict__ wy, const float* __restrict__ wx,
        const float* __restrict__ bin, const float* __restrict__ wh,
        const float* __restrict__ bh, const float* __restrict__ wo,
        const float* __restrict__ bo, float* __restrict__ out) {
    extern __shared__ float sm[];
    const int cta = blockIdx.x, tid = threadIdx.x;
    const int ctabase = cta * 8;
    const int w = tid >> 5, lane = tid & 31;
    const int ks = lane >> 4, rg = lane & 15;

    // --- one-time: load this CTA's 8-column weight slices ---
    for (int i = tid; i < 2048; i += NTHREADS) {      // 1024 k x 2 halves
        int k = i >> 1, h = (i & 1) << 2;
        *(float4*)&sm[OFF_WY  + k * 8 + h] = __ldg((const float4*)&wy[(size_t)k * UNITS + ctabase + h]);
        *(float4*)&sm[OFF_WH0 + k * 8 + h] = __ldg((const float4*)&wh[(size_t)k * UNITS + ctabase + h]);
        *(float4*)&sm[OFF_WH1 + k * 8 + h] = __ldg((const float4*)&wh[(size_t)(UNITS * UNITS) + (size_t)k * UNITS + ctabase + h]);
        *(float4*)&sm[OFF_WO  + k * 8 + h] = __ldg((const float4*)&wo[(size_t)k * UNITS + ctabase + h]);
    }
    for (int i = tid; i < 1024; i += NTHREADS) {      // 512 k x 2 halves
        int k = i >> 1, h = (i & 1) << 2;
        *(float4*)&sm[OFF_WX + k * 8 + h] = __ldg((const float4*)&wx[(size_t)k * UNITS + ctabase + h]);
    }
    if (tid < 8) {
        sm[OFF_B      + tid] = __ldg(&bin[ctabase + tid]);
        sm[OFF_B + 8  + tid] = __ldg(&bh[ctabase + tid]);
        sm[OFF_B + 16 + tid] = __ldg(&bh[UNITS + ctabase + tid]);
        sm[OFF_B + 24 + tid] = __ldg(&bo[ctabase + tid]);
    }
    __syncthreads();

    unsigned e = 0;
    build_xeT(cta, tid, 0, 0, x, emb);
    gbar(cta, tid, ++e);

    for (int t = 0; t < SEQ; t++) {
        float acc[4][8];

        // ---- layer 0: lrelu(y*Wy + xe*Wx + b_in) -> hA ----
        #pragma unroll
        for (int i = 0; i < 4; i++)
            #pragma unroll
            for (int c = 0; c < 8; c++) acc[i][c] = 0.f;
        gemm_pass(sm, g_yT, OFF_WY, 1024, acc, w, ks, rg);
        gemm_pass(sm, g_xeT[t & 1], OFF_WX, 512, acc, w, ks, rg);
        reduce_epi<0>(sm, acc, g_hAT, nullptr, OFF_B, ctabase, t, w, ks, rg);
        gbar(cta, tid, ++e);

        if (t + 1 < SEQ) build_xeT(cta, tid, (t + 1) & 1, t + 1, x, emb);

        // ---- layer 1 ----
        #pragma unroll
        for (int i = 0; i < 4; i++)
            #pragma unroll
            for (int c = 0; c < 8; c++) acc[i][c] = 0.f;
        gemm_pass(sm, g_hAT, OFF_WH0, 1024, acc, w, ks, rg);
        reduce_epi<0>(sm, acc, g_hBT, nullptr, OFF_B + 8, ctabase, t, w, ks, rg);
        gbar(cta, tid, ++e);

        // ---- layer 2 ----
        #pragma unroll
        for (int i = 0; i < 4; i++)
            #pragma unroll
            for (int c = 0; c < 8; c++) acc[i][c] = 0.f;
        gemm_pass(sm, g_hBT, OFF_WH1, 1024, acc, w, ks, rg);
        reduce_epi<0>(sm, acc, g_hAT, nullptr, OFF_B + 16, ctabase, t, w, ks, rg);
        gbar(cta, tid, ++e);

        // ---- layer 3: y += h*Wout + b_out ; write out[:, t, :] ----
        #pragma unroll
        for (int i = 0; i < 4; i++)
            #pragma unroll
            for (int c = 0; c < 8; c++) acc[i][c] = 0.f;
        gemm_pass(sm, g_hAT, OFF_WO, 1024, acc, w, ks, rg);
        reduce_epi<1>(sm, acc, g_yT, out, OFF_B + 24, ctabase, t, w, ks, rg);
        gbar(cta, tid, ++e);
    }
}

extern "C" void kernel_launch(void* const* d_in, const int* in_sizes, int n_in,
                              void* d_out, int out_size) {
    const int*   x    = (const int*)  d_in[0];
    const float* emb  = (const float*)d_in[1];
    const float* wy   = (const float*)d_in[2];
    const float* wx   = (const float*)d_in[3];
    const float* bin  = (const float*)d_in[4];
    const float* wh   = (const float*)d_in[5];
    const float* bh   = (const float*)d_in[6];
    const float* wo   = (const float*)d_in[7];
    const float* bo   = (const float*)d_in[8];
    const float* h0   = (const float*)d_in[9];
    float* out = (float*)d_out;

    cudaFuncSetAttribute(hw_main, cudaFuncAttributeMaxDynamicSharedMemorySize, SMEM_BYTES);

    hw_init<<<NCTA, 256>>>(h0);
    hw_main<<<NCTA, NTHREADS, SMEM_BYTES>>>(x, emb, wy, wx, bin, wh, bh, wo, bo, out);
}

// round 10
// speedup vs baseline: 1.6216x; 1.4145x over previous
#include <cuda_runtime.h>
#include <cuda_bf16.h>
#include <cstdint>
#include <cstddef>

// ---------------------------------------------------------------------------
// HighwayLayerDiscrete — persistent HMMA (mma.sync bf16) kernel, v6.
// tcgen05 is unavailable (harness targets sm_103 without 'a'); use the
// portable m16n8k16 bf16 tensor-core path with 3-term hi/lo split
// (hi*Whi + hi*Wlo + lo*Whi) for ~fp32 accuracy.
//
// 64 CTAs x 256 threads (8 warps = 4 m-tiles x 2 k-halves). Each CTA owns a
// 16-column slice of every layer. Activations are exchanged through L2 in
// *A-fragment layout* (one uint4 ldcg per lane per k-tile, hi+lo buffers);
// weights pre-packed in B-fragment layout. The D fragment maps 1:1 onto the
// next layer's A fragment, so the epilogue converts in registers.
// The embedding projection emb[x]*Wx is precomputed for ALL t in a parallel
// prologue GEMM -> the serial chain is exactly 4 GEMMs/step.
// Grid barrier = release/acquire epoch flags (64 CTAs co-resident).
// ---------------------------------------------------------------------------

#define NCTA  64
#define UNITS 1024
#define EMBED 512
#define BATCH 64
#define SEQ   256
#define ALPHA 0.2f

// ---- static global scratch ----
// weights, B-frag layout: [cta][ktile][split][lane] uint4
__device__ uint4 g_wy [64*64*2*32];
__device__ uint4 g_wh0[64*64*2*32];
__device__ uint4 g_wh1[64*64*2*32];
__device__ uint4 g_wo [64*64*2*32];
__device__ uint4 g_wx [64*32*2*32];
// activations, A-frag layout: [ktile(=cta)][mtile][split][lane] uint4
__device__ uint4 g_y  [64*4*2*32];
__device__ uint4 g_hA [64*4*2*32];
__device__ uint4 g_hB [64*4*2*32];
// precomputed xe*Wx in D-frag layout: [t][slice][mtile][ntile][lane] float4
__device__ float4 g_projx[(size_t)256*64*4*2*32];   // 64 MB
__device__ unsigned g_flags[NCTA*32];

// ---------------- helpers ----------------
__device__ __forceinline__ void pksplit(float a, float b, uint32_t& hi, uint32_t& lo){
    __nv_bfloat162 H, L;
    H.x = __float2bfloat16_rn(a); H.y = __float2bfloat16_rn(b);
    L.x = __float2bfloat16_rn(a - __bfloat162float(H.x));
    L.y = __float2bfloat16_rn(b - __bfloat162float(H.y));
    hi = reinterpret_cast<uint32_t&>(H);
    lo = reinterpret_cast<uint32_t&>(L);
}
__device__ __forceinline__ void mma16816(float d[4], const uint4& a, uint32_t b0, uint32_t b1){
    asm("mma.sync.aligned.m16n8k16.row.col.f32.bf16.bf16.f32 "
        "{%0,%1,%2,%3}, {%4,%5,%6,%7}, {%8,%9}, {%0,%1,%2,%3};"
        : "+f"(d[0]), "+f"(d[1]), "+f"(d[2]), "+f"(d[3])
        : "r"(a.x), "r"(a.y), "r"(a.z), "r"(a.w), "r"(b0), "r"(b1));
}
__device__ __forceinline__ unsigned ld_acq(const unsigned* p){
    unsigned v;
    asm volatile("ld.acquire.gpu.global.u32 %0, [%1];" : "=r"(v) : "l"(p) : "memory");
    return v;
}
__device__ __forceinline__ void st_rel(unsigned* p, unsigned v){
    asm volatile("st.release.gpu.global.u32 [%0], %1;" :: "l"(p), "r"(v) : "memory");
}
// grid barrier (all 64 CTAs co-resident: 1 CTA/SM, 64 <= 148 SMs)
__device__ __forceinline__ void gbar(int cta, int tid, unsigned e){
    __syncthreads();
    if (tid == 0) st_rel(&g_flags[cta*32], e);
    if (tid < NCTA){
        while (ld_acq(&g_flags[tid*32]) < e) { }
    }
    __syncthreads();
}

// ---------------- prologue: pack weights into B-frag hi/lo ----------------
__device__ __forceinline__ void pack_w(const float* __restrict__ W, uint4* __restrict__ G,
                                       int cta, int kt, int lane, int nkt){
    int t2 = (lane & 3) * 2, g = lane >> 2, k0 = kt * 16;
    uint32_t h[4], l[4];
    #pragma unroll
    for (int nt = 0; nt < 2; nt++){
        int n = cta*16 + nt*8 + g;
        float e0 = __ldg(&W[(size_t)(k0+t2  )*UNITS + n]);
        float e1 = __ldg(&W[(size_t)(k0+t2+1)*UNITS + n]);
        float e2 = __ldg(&W[(size_t)(k0+t2+8)*UNITS + n]);
        float e3 = __ldg(&W[(size_t)(k0+t2+9)*UNITS + n]);
        pksplit(e0, e1, h[nt*2],   l[nt*2]);
        pksplit(e2, e3, h[nt*2+1], l[nt*2+1]);
    }
    size_t base = ((size_t)(cta*nkt + kt)*2)*32 + lane;
    G[base]      = make_uint4(h[0], h[1], h[2], h[3]);
    G[base + 32] = make_uint4(l[0], l[1], l[2], l[3]);
}

__global__ void hw_split(const float* __restrict__ wy, const float* __restrict__ wx,
                         const float* __restrict__ wh, const float* __restrict__ wo){
    int b = blockIdx.x, tid = threadIdx.x;
    if (b == 0 && tid < NCTA) __stcg(&g_flags[tid*32], 0u);
    if (b < 2048){                             // 4 big matrices, 512 blocks each
        long id = (long)b*256 + tid;           // 0 .. 524287
        int m = (int)(id >> 17);
        int r = (int)(id & 131071);
        const float* W = (m==0) ? wy : (m==1) ? wh : (m==2) ? wh + 1024*1024 : wo;
        uint4* G       = (m==0) ? g_wy : (m==1) ? g_wh0 : (m==2) ? g_wh1 : g_wo;
        int cta = r >> 11, kt = (r >> 5) & 63, lane = r & 31;
        pack_w(W, G, cta, kt, lane, 64);
    } else {                                   // wx: 256 blocks
        int r = (b - 2048)*256 + tid;          // 0 .. 65535
        int cta = r >> 10, kt = (r >> 5) & 31, lane = r & 31;
        pack_w(wx, g_wx, cta, kt, lane, 32);
    }
}

// ---------------- prologue: proj_x[t] = emb[x[:,t]] * Wx (all t parallel) ---
// block = (t, slice-group of 4). Gathers the t's activation into smem in
// A-frag layout (hi+lo, 128KB), then 8 warps (4 mtiles x 2 khalves) GEMM.
__global__ void __launch_bounds__(256, 1)
hw_projx(const int* __restrict__ x, const float* __restrict__ emb){
    extern __shared__ uint4 sA[];              // 8192 uint4 = 128 KB (reused as red)
    __shared__ int sidx[BATCH];
    int t = blockIdx.x >> 4, sg = blockIdx.x & 15;
    int tid = threadIdx.x, w = tid >> 5, lane = tid & 31;

    if (tid < BATCH) sidx[tid] = __ldg(&x[tid*SEQ + t]);
    __syncthreads();

    // gather A fragments: 32 ktiles x 4 mtiles x 32 lanes
    for (int it = 0; it < 16; it++){
        int item = it*256 + tid;
        int kt = item >> 7, m = (item >> 5) & 3, ln = item & 31;
        int t2 = (ln & 3)*2, g = ln >> 2;
        int r0 = m*16 + g, r1 = r0 + 8;
        const float* e0p = emb + (size_t)sidx[r0]*EMBED + kt*16;
        const float* e1p = emb + (size_t)sidx[r1]*EMBED + kt*16;
        float2 p00 = *(const float2*)(e0p + t2);
        float2 p01 = *(const float2*)(e0p + t2 + 8);
        float2 p10 = *(const float2*)(e1p + t2);
        float2 p11 = *(const float2*)(e1p + t2 + 8);
        uint4 FH, FL;
        pksplit(p00.x, p00.y, FH.x, FL.x);     // a0: row g,  k t2,t2+1
        pksplit(p10.x, p10.y, FH.y, FL.y);     // a1: row g+8
        pksplit(p01.x, p01.y, FH.z, FL.z);     // a2: row g,  k t2+8,+9
        pksplit(p11.x, p11.y, FH.w, FL.w);     // a3: row g+8
        sA[((kt*4 + m)*2 + 0)*32 + ln] = FH;
        sA[((kt*4 + m)*2 + 1)*32 + ln] = FL;
    }
    __syncthreads();

    int m = w & 3, kh = w >> 2;
    float acc[4][2][4];
    #pragma unroll
    for (int sl = 0; sl < 4; sl++)
        #pragma unroll
        for (int nt = 0; nt < 2; nt++)
            #pragma unroll
            for (int j = 0; j < 4; j++) acc[sl][nt][j] = 0.f;

    for (int i = 0; i < 16; i++){
        int kt = kh*16 + i;
        uint4 Ahi = sA[((kt*4 + m)*2 + 0)*32 + lane];
        uint4 Alo = sA[((kt*4 + m)*2 + 1)*32 + lane];
        #pragma unroll
        for (int sl = 0; sl < 4; sl++){
            int slice = sg*4 + sl;
            const uint4* bp = &g_wx[((size_t)(slice*32 + kt)*2)*32 + lane];
            uint4 Bhi = __ldg(bp);
            uint4 Blo = __ldg(bp + 32);
            mma16816(acc[sl][0], Ahi, Bhi.x, Bhi.y);
            mma16816(acc[sl][0], Ahi, Blo.x, Blo.y);
            mma16816(acc[sl][0], Alo, Bhi.x, Bhi.y);
            mma16816(acc[sl][1], Ahi, Bhi.z, Bhi.w);
            mma16816(acc[sl][1], Ahi, Blo.z, Blo.w);
            mma16816(acc[sl][1], Alo, Bhi.z, Bhi.w);
        }
    }
    __syncthreads();
    float4* red = (float4*)sA;
    if (kh == 1){
        #pragma unroll
        for (int sl = 0; sl < 4; sl++)
            #pragma unroll
            for (int nt = 0; nt < 2; nt++)
                red[(m*32 + lane)*8 + sl*2 + nt] =
                    make_float4(acc[sl][nt][0], acc[sl][nt][1], acc[sl][nt][2], acc[sl][nt][3]);
    }
    __syncthreads();
    if (kh == 0){
        #pragma unroll
        for (int sl = 0; sl < 4; sl++){
            int slice = sg*4 + sl;
            #pragma unroll
            for (int nt = 0; nt < 2; nt++){
                float4 r = red[(m*32 + lane)*8 + sl*2 + nt];
                g_projx[((((size_t)t*64 + slice)*4 + m)*2 + nt)*32 + lane] =
                    make_float4(acc[sl][nt][0] + r.x, acc[sl][nt][1] + r.y,
                                acc[sl][nt][2] + r.z, acc[sl][nt][3] + r.w);
            }
        }
    }
}

// ---------------- main persistent kernel ----------------
// MODE 0: +projx, lrelu.  MODE 1: lrelu.  MODE 2: residual y, write out.
template<int MODE>
__device__ __forceinline__ void do_layer(
    int cta, int m, int kh, int lane,
    const uint4* __restrict__ actin, const uint4* __restrict__ wmat,
    uint4* __restrict__ actout, const float* __restrict__ bias16,
    float4* red, float yacc[2][4], float* __restrict__ out, int t)
{
    float acc[2][4];
    #pragma unroll
    for (int nt = 0; nt < 2; nt++)
        #pragma unroll
        for (int j = 0; j < 4; j++) acc[nt][j] = 0.f;

    const uint4* wb = wmat + (size_t)cta*(64*2*32);
    #pragma unroll 4
    for (int i = 0; i < 32; i++){
        int kt = kh*32 + i;
        const uint4* ap = actin + ((kt*4 + m)*2)*32 + lane;
        uint4 Ahi = __ldcg(ap);
        uint4 Alo = __ldcg(ap + 32);
        const uint4* bp = wb + (kt*2)*32 + lane;
        uint4 Bhi = __ldg(bp);
        uint4 Blo = __ldg(bp + 32);
        mma16816(acc[0], Ahi, Bhi.x, Bhi.y);
        mma16816(acc[0], Ahi, Blo.x, Blo.y);
        mma16816(acc[0], Alo, Bhi.x, Bhi.y);
        mma16816(acc[1], Ahi, Bhi.z, Bhi.w);
        mma16816(acc[1], Ahi, Blo.z, Blo.w);
        mma16816(acc[1], Alo, Bhi.z, Bhi.w);
    }
    __syncthreads();
    if (kh == 1){
        red[(m*32 + lane)*2 + 0] = make_float4(acc[0][0], acc[0][1], acc[0][2], acc[0][3]);
        red[(m*32 + lane)*2 + 1] = make_float4(acc[1][0], acc[1][1], acc[1][2], acc[1][3]);
    }
    __syncthreads();
    if (kh == 0){
        float4 r0 = red[(m*32 + lane)*2 + 0];
        float4 r1 = red[(m*32 + lane)*2 + 1];
        acc[0][0] += r0.x; acc[0][1] += r0.y; acc[0][2] += r0.z; acc[0][3] += r0.w;
        acc[1][0] += r1.x; acc[1][1] += r1.y; acc[1][2] += r1.z; acc[1][3] += r1.w;
        int t2 = (lane & 3)*2, g = lane >> 2;
        #pragma unroll
        for (int nt = 0; nt < 2; nt++){
            float b0 = bias16[nt*8 + t2], b1 = bias16[nt*8 + t2 + 1];
            acc[nt][0] += b0; acc[nt][1] += b1; acc[nt][2] += b0; acc[nt][3] += b1;
        }
        if (MODE == 0){
            const float4* pp = &g_projx[((((size_t)t*64 + cta)*4 + m)*2)*32 + lane];
            float4 p0 = __ldcg(pp);
            float4 p1 = __ldcg(pp + 32);
            acc[0][0] += p0.x; acc[0][1] += p0.y; acc[0][2] += p0.z; acc[0][3] += p0.w;
            acc[1][0] += p1.x; acc[1][1] += p1.y; acc[1][2] += p1.z; acc[1][3] += p1.w;
        }
        float v[2][4];
        if (MODE <= 1){
            #pragma unroll
            for (int nt = 0; nt < 2; nt++)
                #pragma unroll
                for (int j = 0; j < 4; j++){
                    float s = acc[nt][j];
                    v[nt][j] = s > 0.f ? s : ALPHA*s;
                }
        } else {
            #pragma unroll
            for (int nt = 0; nt < 2; nt++)
                #pragma unroll
                for (int j = 0; j < 4; j++){
                    yacc[nt][j] += acc[nt][j];
                    v[nt][j] = yacc[nt][j];
                }
            int b0r = m*16 + g;
            #pragma unroll
            for (int nt = 0; nt < 2; nt++){
                int u = cta*16 + nt*8 + t2;
                __stcg((float2*)&out[(size_t)b0r*(SEQ*UNITS) + (size_t)t*UNITS + u],
                       make_float2(v[nt][0], v[nt][1]));
                __stcg((float2*)&out[(size_t)(b0r+8)*(SEQ*UNITS) + (size_t)t*UNITS + u],
                       make_float2(v[nt][2], v[nt][3]));
            }
        }
        // D-frag -> next layer A-frag (register-exact mapping), hi/lo split
        uint4 FH, FL;
        pksplit(v[0][0], v[0][1], FH.x, FL.x);
        pksplit(v[0][2], v[0][3], FH.y, FL.y);
        pksplit(v[1][0], v[1][1], FH.z, FL.z);
        pksplit(v[1][2], v[1][3], FH.w, FL.w);
        uint4* op = actout + ((cta*4 + m)*2)*32 + lane;
        __stcg(op, FH);
        __stcg(op + 32, FL);
    }
}

__global__ void __launch_bounds__(256, 1)
hw_main(const float* __restrict__ bin, const float* __restrict__ bh,
        const float* __restrict__ bo, const float* __restrict__ h0,
        float* __restrict__ out)
{
    __shared__ float4 sred[4*32*2];
    __shared__ float sbias[4][16];
    int cta = blockIdx.x, tid = threadIdx.x, w = tid >> 5, lane = tid & 31;
    int m = w & 3, kh = w >> 2;
    int t2 = (lane & 3)*2;

    if (tid < 64){
        int l = tid >> 4, c = tid & 15;
        float v = (l==0) ? __ldg(&bin[cta*16 + c])
                : (l==1) ? __ldg(&bh[cta*16 + c])
                : (l==2) ? __ldg(&bh[1024 + cta*16 + c])
                         : __ldg(&bo[cta*16 + c]);
        sbias[l][c] = v;
    }

    float yacc[2][4];
    if (kh == 0){
        #pragma unroll
        for (int nt = 0; nt < 2; nt++){
            int n = cta*16 + nt*8 + t2;
            float v0 = __ldg(&h0[n]), v1 = __ldg(&h0[n+1]);
            yacc[nt][0] = v0; yacc[nt][1] = v1; yacc[nt][2] = v0; yacc[nt][3] = v1;
        }
        // publish initial y fragment
        uint4 FH, FL;
        pksplit(yacc[0][0], yacc[0][1], FH.x, FL.x);
        pksplit(yacc[0][2], yacc[0][3], FH.y, FL.y);
        pksplit(yacc[1][0], yacc[1][1], FH.z, FL.z);
        pksplit(yacc[1][2], yacc[1][3], FH.w, FL.w);
        uint4* op = g_y + ((cta*4 + m)*2)*32 + lane;
        __stcg(op, FH);
        __stcg(op + 32, FL);
    }
    __syncthreads();

    unsigned e = 0;
    gbar(cta, tid, ++e);

    for (int t = 0; t < SEQ; t++){
        do_layer<0>(cta, m, kh, lane, g_y,  g_wy,  g_hA, sbias[0], sred, yacc, out, t);
        gbar(cta, tid, ++e);
        do_layer<1>(cta, m, kh, lane, g_hA, g_wh0, g_hB, sbias[1], sred, yacc, out, t);
        gbar(cta, tid, ++e);
        do_layer<1>(cta, m, kh, lane, g_hB, g_wh1, g_hA, sbias[2], sred, yacc, out, t);
        gbar(cta, tid, ++e);
        do_layer<2>(cta, m, kh, lane, g_hA, g_wo,  g_y,  sbias[3], sred, yacc, out, t);
        gbar(cta, tid, ++e);
    }
}

extern "C" void kernel_launch(void* const* d_in, const int* in_sizes, int n_in,
                              void* d_out, int out_size){
    const int*   x   = (const int*)  d_in[0];
    const float* emb = (const float*)d_in[1];
    const float* wy  = (const float*)d_in[2];
    const float* wx  = (const float*)d_in[3];
    const float* bin = (const float*)d_in[4];
    const float* wh  = (const float*)d_in[5];
    const float* bh  = (const float*)d_in[6];
    const float* wo  = (const float*)d_in[7];
    const float* bo  = (const float*)d_in[8];
    const float* h0  = (const float*)d_in[9];
    float* out = (float*)d_out;

    cudaFuncSetAttribute(hw_projx, cudaFuncAttributeMaxDynamicSharedMemorySize, 131072);

    hw_split<<<2304, 256>>>(wy, wx, wh, wo);
    hw_projx<<<4096, 256, 131072>>>(x, emb);
    hw_main<<<NCTA, 256>>>(bin, bh, bo, h0, out);
}

// round 11
// speedup vs baseline: 1.9244x; 1.1867x over previous
#include <cuda_runtime.h>
#include <cuda_bf16.h>
#include <cstdint>
#include <cstddef>

// ---------------------------------------------------------------------------
// HighwayLayerDiscrete — persistent HMMA (mma.sync bf16) kernel, v7.
// v6 -> v7: hw_main goes 256 -> 512 threads (16 warps = 4 m-tiles x 4
// k-quarters). Same total MMA/load work per SMSP, but 4 warps/scheduler hide
// L2 latency under tensor issue (v6 had 2 and serialized). Reduction tree now
// combines 4 k-partials through smem.
// 3-term hi/lo bf16 split (hi*Whi + hi*Wlo + lo*Whi) ~ fp32 accuracy.
// Activations exchanged through L2 in A-fragment layout; weights pre-packed
// in B-fragment layout; D-frag == next A-frag (register-exact remap).
// proj_x = emb[x]*Wx precomputed for all t by a parallel prologue.
// ---------------------------------------------------------------------------

#define NCTA  64
#define UNITS 1024
#define EMBED 512
#define BATCH 64
#define SEQ   256
#define ALPHA 0.2f

// ---- static global scratch ----
__device__ uint4 g_wy [64*64*2*32];
__device__ uint4 g_wh0[64*64*2*32];
__device__ uint4 g_wh1[64*64*2*32];
__device__ uint4 g_wo [64*64*2*32];
__device__ uint4 g_wx [64*32*2*32];
__device__ uint4 g_y  [64*4*2*32];
__device__ uint4 g_hA [64*4*2*32];
__device__ uint4 g_hB [64*4*2*32];
__device__ float4 g_projx[(size_t)256*64*4*2*32];   // 64 MB
__device__ unsigned g_flags[NCTA*32];

// ---------------- helpers ----------------
__device__ __forceinline__ void pksplit(float a, float b, uint32_t& hi, uint32_t& lo){
    __nv_bfloat162 H, L;
    H.x = __float2bfloat16_rn(a); H.y = __float2bfloat16_rn(b);
    L.x = __float2bfloat16_rn(a - __bfloat162float(H.x));
    L.y = __float2bfloat16_rn(b - __bfloat162float(H.y));
    hi = reinterpret_cast<uint32_t&>(H);
    lo = reinterpret_cast<uint32_t&>(L);
}
__device__ __forceinline__ void mma16816(float d[4], const uint4& a, uint32_t b0, uint32_t b1){
    asm("mma.sync.aligned.m16n8k16.row.col.f32.bf16.bf16.f32 "
        "{%0,%1,%2,%3}, {%4,%5,%6,%7}, {%8,%9}, {%0,%1,%2,%3};"
        : "+f"(d[0]), "+f"(d[1]), "+f"(d[2]), "+f"(d[3])
        : "r"(a.x), "r"(a.y), "r"(a.z), "r"(a.w), "r"(b0), "r"(b1));
}
__device__ __forceinline__ unsigned ld_acq(const unsigned* p){
    unsigned v;
    asm volatile("ld.acquire.gpu.global.u32 %0, [%1];" : "=r"(v) : "l"(p) : "memory");
    return v;
}
__device__ __forceinline__ void st_rel(unsigned* p, unsigned v){
    asm volatile("st.release.gpu.global.u32 [%0], %1;" :: "l"(p), "r"(v) : "memory");
}
__device__ __forceinline__ void gbar(int cta, int tid, unsigned e){
    __syncthreads();
    if (tid == 0) st_rel(&g_flags[cta*32], e);
    if (tid < NCTA){
        while (ld_acq(&g_flags[tid*32]) < e) { }
    }
    __syncthreads();
}

// ---------------- prologue: pack weights into B-frag hi/lo ----------------
__device__ __forceinline__ void pack_w(const float* __restrict__ W, uint4* __restrict__ G,
                                       int cta, int kt, int lane, int nkt){
    int t2 = (lane & 3) * 2, g = lane >> 2, k0 = kt * 16;
    uint32_t h[4], l[4];
    #pragma unroll
    for (int nt = 0; nt < 2; nt++){
        int n = cta*16 + nt*8 + g;
        float e0 = __ldg(&W[(size_t)(k0+t2  )*UNITS + n]);
        float e1 = __ldg(&W[(size_t)(k0+t2+1)*UNITS + n]);
        float e2 = __ldg(&W[(size_t)(k0+t2+8)*UNITS + n]);
        float e3 = __ldg(&W[(size_t)(k0+t2+9)*UNITS + n]);
        pksplit(e0, e1, h[nt*2],   l[nt*2]);
        pksplit(e2, e3, h[nt*2+1], l[nt*2+1]);
    }
    size_t base = ((size_t)(cta*nkt + kt)*2)*32 + lane;
    G[base]      = make_uint4(h[0], h[1], h[2], h[3]);
    G[base + 32] = make_uint4(l[0], l[1], l[2], l[3]);
}

__global__ void hw_split(const float* __restrict__ wy, const float* __restrict__ wx,
                         const float* __restrict__ wh, const float* __restrict__ wo){
    int b = blockIdx.x, tid = threadIdx.x;
    if (b == 0 && tid < NCTA) __stcg(&g_flags[tid*32], 0u);
    if (b < 2048){
        long id = (long)b*256 + tid;
        int m = (int)(id >> 17);
        int r = (int)(id & 131071);
        const float* W = (m==0) ? wy : (m==1) ? wh : (m==2) ? wh + 1024*1024 : wo;
        uint4* G       = (m==0) ? g_wy : (m==1) ? g_wh0 : (m==2) ? g_wh1 : g_wo;
        int cta = r >> 11, kt = (r >> 5) & 63, lane = r & 31;
        pack_w(W, G, cta, kt, lane, 64);
    } else {
        int r = (b - 2048)*256 + tid;
        int cta = r >> 10, kt = (r >> 5) & 31, lane = r & 31;
        pack_w(wx, g_wx, cta, kt, lane, 32);
    }
}

// ---------------- prologue: proj_x[t] = emb[x[:,t]] * Wx ----------------
__global__ void __launch_bounds__(256, 1)
hw_projx(const int* __restrict__ x, const float* __restrict__ emb){
    extern __shared__ uint4 sA[];              // 128 KB
    __shared__ int sidx[BATCH];
    int t = blockIdx.x >> 4, sg = blockIdx.x & 15;
    int tid = threadIdx.x, w = tid >> 5, lane = tid & 31;

    if (tid < BATCH) sidx[tid] = __ldg(&x[tid*SEQ + t]);
    __syncthreads();

    for (int it = 0; it < 16; it++){
        int item = it*256 + tid;
        int kt = item >> 7, m = (item >> 5) & 3, ln = item & 31;
        int t2 = (ln & 3)*2, g = ln >> 2;
        int r0 = m*16 + g, r1 = r0 + 8;
        const float* e0p = emb + (size_t)sidx[r0]*EMBED + kt*16;
        const float* e1p = emb + (size_t)sidx[r1]*EMBED + kt*16;
        float2 p00 = *(const float2*)(e0p + t2);
        float2 p01 = *(const float2*)(e0p + t2 + 8);
        float2 p10 = *(const float2*)(e1p + t2);
        float2 p11 = *(const float2*)(e1p + t2 + 8);
        uint4 FH, FL;
        pksplit(p00.x, p00.y, FH.x, FL.x);
        pksplit(p10.x, p10.y, FH.y, FL.y);
        pksplit(p01.x, p01.y, FH.z, FL.z);
        pksplit(p11.x, p11.y, FH.w, FL.w);
        sA[((kt*4 + m)*2 + 0)*32 + ln] = FH;
        sA[((kt*4 + m)*2 + 1)*32 + ln] = FL;
    }
    __syncthreads();

    int m = w & 3, kh = w >> 2;
    float acc[4][2][4];
    #pragma unroll
    for (int sl = 0; sl < 4; sl++)
        #pragma unroll
        for (int nt = 0; nt < 2; nt++)
            #pragma unroll
            for (int j = 0; j < 4; j++) acc[sl][nt][j] = 0.f;

    for (int i = 0; i < 16; i++){
        int kt = kh*16 + i;
        uint4 Ahi = sA[((kt*4 + m)*2 + 0)*32 + lane];
        uint4 Alo = sA[((kt*4 + m)*2 + 1)*32 + lane];
        #pragma unroll
        for (int sl = 0; sl < 4; sl++){
            int slice = sg*4 + sl;
            const uint4* bp = &g_wx[((size_t)(slice*32 + kt)*2)*32 + lane];
            uint4 Bhi = __ldg(bp);
            uint4 Blo = __ldg(bp + 32);
            mma16816(acc[sl][0], Ahi, Bhi.x, Bhi.y);
            mma16816(acc[sl][0], Ahi, Blo.x, Blo.y);
            mma16816(acc[sl][0], Alo, Bhi.x, Bhi.y);
            mma16816(acc[sl][1], Ahi, Bhi.z, Bhi.w);
            mma16816(acc[sl][1], Ahi, Blo.z, Blo.w);
            mma16816(acc[sl][1], Alo, Bhi.z, Bhi.w);
        }
    }
    __syncthreads();
    float4* red = (float4*)sA;
    if (kh == 1){
        #pragma unroll
        for (int sl = 0; sl < 4; sl++)
            #pragma unroll
            for (int nt = 0; nt < 2; nt++)
                red[(m*32 + lane)*8 + sl*2 + nt] =
                    make_float4(acc[sl][nt][0], acc[sl][nt][1], acc[sl][nt][2], acc[sl][nt][3]);
    }
    __syncthreads();
    if (kh == 0){
        #pragma unroll
        for (int sl = 0; sl < 4; sl++){
            int slice = sg*4 + sl;
            #pragma unroll
            for (int nt = 0; nt < 2; nt++){
                float4 r = red[(m*32 + lane)*8 + sl*2 + nt];
                g_projx[((((size_t)t*64 + slice)*4 + m)*2 + nt)*32 + lane] =
                    make_float4(acc[sl][nt][0] + r.x, acc[sl][nt][1] + r.y,
                                acc[sl][nt][2] + r.z, acc[sl][nt][3] + r.w);
            }
        }
    }
}

// ---------------- main persistent kernel (512 threads, 16 warps) ----------
// warp w: m = w&3 (m-tile), kq = w>>2 (k-quarter, 16 ktiles each).
// MODE 0: +projx, lrelu.  MODE 1: lrelu.  MODE 2: residual y, write out.
template<int MODE>
__device__ __forceinline__ void do_layer(
    int cta, int m, int kq, int lane,
    const uint4* __restrict__ actin, const uint4* __restrict__ wmat,
    uint4* __restrict__ actout, const float* __restrict__ bias16,
    float4* red, float yacc[2][4], float* __restrict__ out, int t)
{
    float acc[2][4];
    #pragma unroll
    for (int nt = 0; nt < 2; nt++)
        #pragma unroll
        for (int j = 0; j < 4; j++) acc[nt][j] = 0.f;

    const uint4* wb = wmat + (size_t)cta*(64*2*32);
    #pragma unroll 8
    for (int i = 0; i < 16; i++){
        int kt = kq*16 + i;
        const uint4* ap = actin + ((kt*4 + m)*2)*32 + lane;
        uint4 Ahi = __ldcg(ap);
        uint4 Alo = __ldcg(ap + 32);
        const uint4* bp = wb + (kt*2)*32 + lane;
        uint4 Bhi = __ldg(bp);
        uint4 Blo = __ldg(bp + 32);
        mma16816(acc[0], Ahi, Bhi.x, Bhi.y);
        mma16816(acc[0], Ahi, Blo.x, Blo.y);
        mma16816(acc[0], Alo, Bhi.x, Bhi.y);
        mma16816(acc[1], Ahi, Bhi.z, Bhi.w);
        mma16816(acc[1], Ahi, Blo.z, Blo.w);
        mma16816(acc[1], Alo, Bhi.z, Bhi.w);
    }
    __syncthreads();
    if (kq > 0){
        red[((kq-1)*4 + m)*64 + lane*2 + 0] =
            make_float4(acc[0][0], acc[0][1], acc[0][2], acc[0][3]);
        red[((kq-1)*4 + m)*64 + lane*2 + 1] =
            make_float4(acc[1][0], acc[1][1], acc[1][2], acc[1][3]);
    }
    __syncthreads();
    if (kq == 0){
        #pragma unroll
        for (int p = 0; p < 3; p++){
            float4 r0 = red[(p*4 + m)*64 + lane*2 + 0];
            float4 r1 = red[(p*4 + m)*64 + lane*2 + 1];
            acc[0][0] += r0.x; acc[0][1] += r0.y; acc[0][2] += r0.z; acc[0][3] += r0.w;
            acc[1][0] += r1.x; acc[1][1] += r1.y; acc[1][2] += r1.z; acc[1][3] += r1.w;
        }
        int t2 = (lane & 3)*2, g = lane >> 2;
        #pragma unroll
        for (int nt = 0; nt < 2; nt++){
            float b0 = bias16[nt*8 + t2], b1 = bias16[nt*8 + t2 + 1];
            acc[nt][0] += b0; acc[nt][1] += b1; acc[nt][2] += b0; acc[nt][3] += b1;
        }
        if (MODE == 0){
            const float4* pp = &g_projx[((((size_t)t*64 + cta)*4 + m)*2)*32 + lane];
            float4 p0 = __ldcg(pp);
            float4 p1 = __ldcg(pp + 32);
            acc[0][0] += p0.x; acc[0][1] += p0.y; acc[0][2] += p0.z; acc[0][3] += p0.w;
            acc[1][0] += p1.x; acc[1][1] += p1.y; acc[1][2] += p1.z; acc[1][3] += p1.w;
        }
        float v[2][4];
        if (MODE <= 1){
            #pragma unroll
            for (int nt = 0; nt < 2; nt++)
                #pragma unroll
                for (int j = 0; j < 4; j++){
                    float s = acc[nt][j];
                    v[nt][j] = s > 0.f ? s : ALPHA*s;
                }
        } else {
            #pragma unroll
            for (int nt = 0; nt < 2; nt++)
                #pragma unroll
                for (int j = 0; j < 4; j++){
                    yacc[nt][j] += acc[nt][j];
                    v[nt][j] = yacc[nt][j];
                }
            int b0r = m*16 + g;
            #pragma unroll
            for (int nt = 0; nt < 2; nt++){
                int u = cta*16 + nt*8 + t2;
                __stcg((float2*)&out[(size_t)b0r*(SEQ*UNITS) + (size_t)t*UNITS + u],
                       make_float2(v[nt][0], v[nt][1]));
                __stcg((float2*)&out[(size_t)(b0r+8)*(SEQ*UNITS) + (size_t)t*UNITS + u],
                       make_float2(v[nt][2], v[nt][3]));
            }
        }
        uint4 FH, FL;
        pksplit(v[0][0], v[0][1], FH.x, FL.x);
        pksplit(v[0][2], v[0][3], FH.y, FL.y);
        pksplit(v[1][0], v[1][1], FH.z, FL.z);
        pksplit(v[1][2], v[1][3], FH.w, FL.w);
        uint4* op = actout + ((cta*4 + m)*2)*32 + lane;
        __stcg(op, FH);
        __stcg(op + 32, FL);
    }
}

__global__ void __launch_bounds__(512, 1)
hw_main(const float* __restrict__ bin, const float* __restrict__ bh,
        const float* __restrict__ bo, const float* __restrict__ h0,
        float* __restrict__ out)
{
    __shared__ float4 sred[3*4*64];            // 3 partials x 4 mtiles x 64
    __shared__ float sbias[4][16];
    int cta = blockIdx.x, tid = threadIdx.x, w = tid >> 5, lane = tid & 31;
    int m = w & 3, kq = w >> 2;
    int t2 = (lane & 3)*2;

    if (tid < 64){
        int l = tid >> 4, c = tid & 15;
        float v = (l==0) ? __ldg(&bin[cta*16 + c])
                : (l==1) ? __ldg(&bh[cta*16 + c])
                : (l==2) ? __ldg(&bh[1024 + cta*16 + c])
                         : __ldg(&bo[cta*16 + c]);
        sbias[l][c] = v;
    }

    float yacc[2][4];
    if (kq == 0){
        #pragma unroll
        for (int nt = 0; nt < 2; nt++){
            int n = cta*16 + nt*8 + t2;
            float v0 = __ldg(&h0[n]), v1 = __ldg(&h0[n+1]);
            yacc[nt][0] = v0; yacc[nt][1] = v1; yacc[nt][2] = v0; yacc[nt][3] = v1;
        }
        uint4 FH, FL;
        pksplit(yacc[0][0], yacc[0][1], FH.x, FL.x);
        pksplit(yacc[0][2], yacc[0][3], FH.y, FL.y);
        pksplit(yacc[1][0], yacc[1][1], FH.z, FL.z);
        pksplit(yacc[1][2], yacc[1][3], FH.w, FL.w);
        uint4* op = g_y + ((cta*4 + m)*2)*32 + lane;
        __stcg(op, FH);
        __stcg(op + 32, FL);
    }
    __syncthreads();

    unsigned e = 0;
    gbar(cta, tid, ++e);

    for (int t = 0; t < SEQ; t++){
        do_layer<0>(cta, m, kq, lane, g_y,  g_wy,  g_hA, sbias[0], sred, yacc, out, t);
        gbar(cta, tid, ++e);
        do_layer<1>(cta, m, kq, lane, g_hA, g_wh0, g_hB, sbias[1], sred, yacc, out, t);
        gbar(cta, tid, ++e);
        do_layer<1>(cta, m, kq, lane, g_hB, g_wh1, g_hA, sbias[2], sred, yacc, out, t);
        gbar(cta, tid, ++e);
        do_layer<2>(cta, m, kq, lane, g_hA, g_wo,  g_y,  sbias[3], sred, yacc, out, t);
        gbar(cta, tid, ++e);
    }
}

extern "C" void kernel_launch(void* const* d_in, const int* in_sizes, int n_in,
                              void* d_out, int out_size){
    const int*   x   = (const int*)  d_in[0];
    const float* emb = (const float*)d_in[1];
    const float* wy  = (const float*)d_in[2];
    const float* wx  = (const float*)d_in[3];
    const float* bin = (const float*)d_in[4];
    const float* wh  = (const float*)d_in[5];
    const float* bh  = (const float*)d_in[6];
    const float* wo  = (const float*)d_in[7];
    const float* bo  = (const float*)d_in[8];
    const float* h0  = (const float*)d_in[9];
    float* out = (float*)d_out;

    cudaFuncSetAttribute(hw_projx, cudaFuncAttributeMaxDynamicSharedMemorySize, 131072);

    hw_split<<<2304, 256>>>(wy, wx, wh, wo);
    hw_projx<<<4096, 256, 131072>>>(x, emb);
    hw_main<<<NCTA, 512>>>(bin, bh, bo, h0, out);
}

// round 12
// speedup vs baseline: 2.5818x; 1.3416x over previous
#include <cuda_runtime.h>
#include <cuda_bf16.h>
#include <cstdint>
#include <cstddef>

// ---------------------------------------------------------------------------
// HighwayLayerDiscrete — persistent HMMA (mma.sync bf16) kernel, v8.
// v7 -> v8: batch rows are independent, so split M=64 into 2 halves:
// 128 CTAs = 64 col-slices x 2 row-halves (was 64 CTAs on 64 of 148 SMs!).
// Two fully independent 64-CTA barrier groups. Per-CTA A traffic, MMA count,
// and epilogue all halve. Warps: 16 = 2 m-tiles x 8 k-eighths.
// 3-term hi/lo bf16 split (hi*Whi + hi*Wlo + lo*Whi) ~ fp32 accuracy.
// Activations exchanged through L2 in A-fragment layout; weights pre-packed
// in B-fragment layout; D-frag == next A-frag (register-exact remap).
// proj_x = emb[x]*Wx precomputed for all t by a parallel prologue.
// ---------------------------------------------------------------------------

#define NCTA  128
#define UNITS 1024
#define EMBED 512
#define BATCH 64
#define SEQ   256
#define ALPHA 0.2f

// ---- static global scratch ----
__device__ uint4 g_wy [64*64*2*32];
__device__ uint4 g_wh0[64*64*2*32];
__device__ uint4 g_wh1[64*64*2*32];
__device__ uint4 g_wo [64*64*2*32];
__device__ uint4 g_wx [64*32*2*32];
__device__ uint4 g_y  [64*4*2*32];
__device__ uint4 g_hA [64*4*2*32];
__device__ uint4 g_hB [64*4*2*32];
__device__ float4 g_projx[(size_t)256*64*4*2*32];   // 64 MB
__device__ unsigned g_flags[NCTA*32];

// ---------------- helpers ----------------
__device__ __forceinline__ void pksplit(float a, float b, uint32_t& hi, uint32_t& lo){
    __nv_bfloat162 H, L;
    H.x = __float2bfloat16_rn(a); H.y = __float2bfloat16_rn(b);
    L.x = __float2bfloat16_rn(a - __bfloat162float(H.x));
    L.y = __float2bfloat16_rn(b - __bfloat162float(H.y));
    hi = reinterpret_cast<uint32_t&>(H);
    lo = reinterpret_cast<uint32_t&>(L);
}
__device__ __forceinline__ void mma16816(float d[4], const uint4& a, uint32_t b0, uint32_t b1){
    asm("mma.sync.aligned.m16n8k16.row.col.f32.bf16.bf16.f32 "
        "{%0,%1,%2,%3}, {%4,%5,%6,%7}, {%8,%9}, {%0,%1,%2,%3};"
        : "+f"(d[0]), "+f"(d[1]), "+f"(d[2]), "+f"(d[3])
        : "r"(a.x), "r"(a.y), "r"(a.z), "r"(a.w), "r"(b0), "r"(b1));
}
__device__ __forceinline__ unsigned ld_acq(const unsigned* p){
    unsigned v;
    asm volatile("ld.acquire.gpu.global.u32 %0, [%1];" : "=r"(v) : "l"(p) : "memory");
    return v;
}
__device__ __forceinline__ void st_rel(unsigned* p, unsigned v){
    asm volatile("st.release.gpu.global.u32 [%0], %1;" :: "l"(p), "r"(v) : "memory");
}
// group-local grid barrier: 64 CTAs of this row-half (all co-resident)
__device__ __forceinline__ void gbar(int cta, int gb, int tid, unsigned e){
    __syncthreads();
    if (tid == 0) st_rel(&g_flags[cta*32], e);
    if (tid < 64){
        while (ld_acq(&g_flags[(gb + tid)*32]) < e) { }
    }
    __syncthreads();
}

// ---------------- prologue: pack weights into B-frag hi/lo ----------------
__device__ __forceinline__ void pack_w(const float* __restrict__ W, uint4* __restrict__ G,
                                       int sl, int kt, int lane, int nkt){
    int t2 = (lane & 3) * 2, g = lane >> 2, k0 = kt * 16;
    uint32_t h[4], l[4];
    #pragma unroll
    for (int nt = 0; nt < 2; nt++){
        int n = sl*16 + nt*8 + g;
        float e0 = __ldg(&W[(size_t)(k0+t2  )*UNITS + n]);
        float e1 = __ldg(&W[(size_t)(k0+t2+1)*UNITS + n]);
        float e2 = __ldg(&W[(size_t)(k0+t2+8)*UNITS + n]);
        float e3 = __ldg(&W[(size_t)(k0+t2+9)*UNITS + n]);
        pksplit(e0, e1, h[nt*2],   l[nt*2]);
        pksplit(e2, e3, h[nt*2+1], l[nt*2+1]);
    }
    size_t base = ((size_t)(sl*nkt + kt)*2)*32 + lane;
    G[base]      = make_uint4(h[0], h[1], h[2], h[3]);
    G[base + 32] = make_uint4(l[0], l[1], l[2], l[3]);
}

__global__ void hw_split(const float* __restrict__ wy, const float* __restrict__ wx,
                         const float* __restrict__ wh, const float* __restrict__ wo){
    int b = blockIdx.x, tid = threadIdx.x;
    if (b == 0 && tid < NCTA) __stcg(&g_flags[tid*32], 0u);
    if (b < 2048){
        long id = (long)b*256 + tid;
        int m = (int)(id >> 17);
        int r = (int)(id & 131071);
        const float* W = (m==0) ? wy : (m==1) ? wh : (m==2) ? wh + 1024*1024 : wo;
        uint4* G       = (m==0) ? g_wy : (m==1) ? g_wh0 : (m==2) ? g_wh1 : g_wo;
        int sl = r >> 11, kt = (r >> 5) & 63, lane = r & 31;
        pack_w(W, G, sl, kt, lane, 64);
    } else {
        int r = (b - 2048)*256 + tid;
        int sl = r >> 10, kt = (r >> 5) & 31, lane = r & 31;
        pack_w(wx, g_wx, sl, kt, lane, 32);
    }
}

// ---------------- prologue: proj_x[t] = emb[x[:,t]] * Wx ----------------
__global__ void __launch_bounds__(256, 1)
hw_projx(const int* __restrict__ x, const float* __restrict__ emb){
    extern __shared__ uint4 sA[];              // 128 KB
    __shared__ int sidx[BATCH];
    int t = blockIdx.x >> 4, sg = blockIdx.x & 15;
    int tid = threadIdx.x, w = tid >> 5, lane = tid & 31;

    if (tid < BATCH) sidx[tid] = __ldg(&x[tid*SEQ + t]);
    __syncthreads();

    for (int it = 0; it < 16; it++){
        int item = it*256 + tid;
        int kt = item >> 7, m = (item >> 5) & 3, ln = item & 31;
        int t2 = (ln & 3)*2, g = ln >> 2;
        int r0 = m*16 + g, r1 = r0 + 8;
        const float* e0p = emb + (size_t)sidx[r0]*EMBED + kt*16;
        const float* e1p = emb + (size_t)sidx[r1]*EMBED + kt*16;
        float2 p00 = *(const float2*)(e0p + t2);
        float2 p01 = *(const float2*)(e0p + t2 + 8);
        float2 p10 = *(const float2*)(e1p + t2);
        float2 p11 = *(const float2*)(e1p + t2 + 8);
        uint4 FH, FL;
        pksplit(p00.x, p00.y, FH.x, FL.x);
        pksplit(p10.x, p10.y, FH.y, FL.y);
        pksplit(p01.x, p01.y, FH.z, FL.z);
        pksplit(p11.x, p11.y, FH.w, FL.w);
        sA[((kt*4 + m)*2 + 0)*32 + ln] = FH;
        sA[((kt*4 + m)*2 + 1)*32 + ln] = FL;
    }
    __syncthreads();

    int m = w & 3, kh = w >> 2;
    float acc[4][2][4];
    #pragma unroll
    for (int sl = 0; sl < 4; sl++)
        #pragma unroll
        for (int nt = 0; nt < 2; nt++)
            #pragma unroll
            for (int j = 0; j < 4; j++) acc[sl][nt][j] = 0.f;

    for (int i = 0; i < 16; i++){
        int kt = kh*16 + i;
        uint4 Ahi = sA[((kt*4 + m)*2 + 0)*32 + lane];
        uint4 Alo = sA[((kt*4 + m)*2 + 1)*32 + lane];
        #pragma unroll
        for (int sl = 0; sl < 4; sl++){
            int slice = sg*4 + sl;
            const uint4* bp = &g_wx[((size_t)(slice*32 + kt)*2)*32 + lane];
            uint4 Bhi = __ldg(bp);
            uint4 Blo = __ldg(bp + 32);
            mma16816(acc[sl][0], Ahi, Bhi.x, Bhi.y);
            mma16816(acc[sl][0], Ahi, Blo.x, Blo.y);
            mma16816(acc[sl][0], Alo, Bhi.x, Bhi.y);
            mma16816(acc[sl][1], Ahi, Bhi.z, Bhi.w);
            mma16816(acc[sl][1], Ahi, Blo.z, Blo.w);
            mma16816(acc[sl][1], Alo, Bhi.z, Bhi.w);
        }
    }
    __syncthreads();
    float4* red = (float4*)sA;
    if (kh == 1){
        #pragma unroll
        for (int sl = 0; sl < 4; sl++)
            #pragma unroll
            for (int nt = 0; nt < 2; nt++)
                red[(m*32 + lane)*8 + sl*2 + nt] =
                    make_float4(acc[sl][nt][0], acc[sl][nt][1], acc[sl][nt][2], acc[sl][nt][3]);
    }
    __syncthreads();
    if (kh == 0){
        #pragma unroll
        for (int sl = 0; sl < 4; sl++){
            int slice = sg*4 + sl;
            #pragma unroll
            for (int nt = 0; nt < 2; nt++){
                float4 r = red[(m*32 + lane)*8 + sl*2 + nt];
                g_projx[((((size_t)t*64 + slice)*4 + m)*2 + nt)*32 + lane] =
                    make_float4(acc[sl][nt][0] + r.x, acc[sl][nt][1] + r.y,
                                acc[sl][nt][2] + r.z, acc[sl][nt][3] + r.w);
            }
        }
    }
}

// ---------------- main persistent kernel (128 CTAs x 512 threads) ----------
// CTA = (slice = cta&63, mh = cta>>6). warp w: lm = w&1 (local mtile),
// kq = w>>1 (k-eighth, 8 ktiles). Global mtile m = mh*2 + lm.
// MODE 0: +projx, lrelu.  MODE 1: lrelu.  MODE 2: residual y, write out.
template<int MODE>
__device__ __forceinline__ void do_layer(
    int slice, int m, int lm, int kq, int lane,
    const uint4* __restrict__ actin, const uint4* __restrict__ wmat,
    uint4* __restrict__ actout, const float* __restrict__ bias16,
    float4* red, float yacc[2][4], float* __restrict__ out, int t)
{
    // prefetch projx addend (layer 0 only, epilogue warps only)
    float4 px0, px1;
    if (MODE == 0 && kq == 0){
        const float4* pp = &g_projx[((((size_t)t*64 + slice)*4 + m)*2)*32 + lane];
        px0 = __ldcg(pp);
        px1 = __ldcg(pp + 32);
    }

    float acc[2][4];
    #pragma unroll
    for (int nt = 0; nt < 2; nt++)
        #pragma unroll
        for (int j = 0; j < 4; j++) acc[nt][j] = 0.f;

    const uint4* wb = wmat + (size_t)slice*(64*2*32);
    #pragma unroll 8
    for (int i = 0; i < 8; i++){
        int kt = kq*8 + i;
        const uint4* ap = actin + ((kt*4 + m)*2)*32 + lane;
        uint4 Ahi = __ldcg(ap);
        uint4 Alo = __ldcg(ap + 32);
        const uint4* bp = wb + (kt*2)*32 + lane;
        uint4 Bhi = __ldg(bp);
        uint4 Blo = __ldg(bp + 32);
        mma16816(acc[0], Ahi, Bhi.x, Bhi.y);
        mma16816(acc[0], Ahi, Blo.x, Blo.y);
        mma16816(acc[0], Alo, Bhi.x, Bhi.y);
        mma16816(acc[1], Ahi, Bhi.z, Bhi.w);
        mma16816(acc[1], Ahi, Blo.z, Blo.w);
        mma16816(acc[1], Alo, Bhi.z, Bhi.w);
    }
    __syncthreads();
    if (kq > 0){
        red[((kq-1)*2 + lm)*64 + lane*2 + 0] =
            make_float4(acc[0][0], acc[0][1], acc[0][2], acc[0][3]);
        red[((kq-1)*2 + lm)*64 + lane*2 + 1] =
            make_float4(acc[1][0], acc[1][1], acc[1][2], acc[1][3]);
    }
    __syncthreads();
    if (kq == 0){
        #pragma unroll
        for (int p = 0; p < 7; p++){
            float4 r0 = red[(p*2 + lm)*64 + lane*2 + 0];
            float4 r1 = red[(p*2 + lm)*64 + lane*2 + 1];
            acc[0][0] += r0.x; acc[0][1] += r0.y; acc[0][2] += r0.z; acc[0][3] += r0.w;
            acc[1][0] += r1.x; acc[1][1] += r1.y; acc[1][2] += r1.z; acc[1][3] += r1.w;
        }
        int t2 = (lane & 3)*2, g = lane >> 2;
        #pragma unroll
        for (int nt = 0; nt < 2; nt++){
            float b0 = bias16[nt*8 + t2], b1 = bias16[nt*8 + t2 + 1];
            acc[nt][0] += b0; acc[nt][1] += b1; acc[nt][2] += b0; acc[nt][3] += b1;
        }
        if (MODE == 0){
            acc[0][0] += px0.x; acc[0][1] += px0.y; acc[0][2] += px0.z; acc[0][3] += px0.w;
            acc[1][0] += px1.x; acc[1][1] += px1.y; acc[1][2] += px1.z; acc[1][3] += px1.w;
        }
        float v[2][4];
        if (MODE <= 1){
            #pragma unroll
            for (int nt = 0; nt < 2; nt++)
                #pragma unroll
                for (int j = 0; j < 4; j++){
                    float s = acc[nt][j];
                    v[nt][j] = s > 0.f ? s : ALPHA*s;
                }
        } else {
            #pragma unroll
            for (int nt = 0; nt < 2; nt++)
                #pragma unroll
                for (int j = 0; j < 4; j++){
                    yacc[nt][j] += acc[nt][j];
                    v[nt][j] = yacc[nt][j];
                }
            int b0r = m*16 + g;
            #pragma unroll
            for (int nt = 0; nt < 2; nt++){
                int u = slice*16 + nt*8 + t2;
                __stcg((float2*)&out[(size_t)b0r*(SEQ*UNITS) + (size_t)t*UNITS + u],
                       make_float2(v[nt][0], v[nt][1]));
                __stcg((float2*)&out[(size_t)(b0r+8)*(SEQ*UNITS) + (size_t)t*UNITS + u],
                       make_float2(v[nt][2], v[nt][3]));
            }
        }
        uint4 FH, FL;
        pksplit(v[0][0], v[0][1], FH.x, FL.x);
        pksplit(v[0][2], v[0][3], FH.y, FL.y);
        pksplit(v[1][0], v[1][1], FH.z, FL.z);
        pksplit(v[1][2], v[1][3], FH.w, FL.w);
        uint4* op = actout + ((slice*4 + m)*2)*32 + lane;
        __stcg(op, FH);
        __stcg(op + 32, FL);
    }
}

__global__ void __launch_bounds__(512, 1)
hw_main(const float* __restrict__ bin, const float* __restrict__ bh,
        const float* __restrict__ bo, const float* __restrict__ h0,
        float* __restrict__ out)
{
    __shared__ float4 sred[7*2*64];            // 7 partials x 2 mtiles x 64
    __shared__ float sbias[4][16];
    int cta = blockIdx.x, tid = threadIdx.x, w = tid >> 5, lane = tid & 31;
    int slice = cta & 63, mh = cta >> 6, gb = mh*64 + 0;  // flag-group base
    int lm = w & 1, kq = w >> 1;
    int m = mh*2 + lm;
    int t2 = (lane & 3)*2;

    if (tid < 64){
        int l = tid >> 4, c = tid & 15;
        float v = (l==0) ? __ldg(&bin[slice*16 + c])
                : (l==1) ? __ldg(&bh[slice*16 + c])
                : (l==2) ? __ldg(&bh[1024 + slice*16 + c])
                         : __ldg(&bo[slice*16 + c]);
        sbias[l][c] = v;
    }

    float yacc[2][4];
    if (kq == 0){
        #pragma unroll
        for (int nt = 0; nt < 2; nt++){
            int n = slice*16 + nt*8 + t2;
            float v0 = __ldg(&h0[n]), v1 = __ldg(&h0[n+1]);
            yacc[nt][0] = v0; yacc[nt][1] = v1; yacc[nt][2] = v0; yacc[nt][3] = v1;
        }
        uint4 FH, FL;
        pksplit(yacc[0][0], yacc[0][1], FH.x, FL.x);
        pksplit(yacc[0][2], yacc[0][3], FH.y, FL.y);
        pksplit(yacc[1][0], yacc[1][1], FH.z, FL.z);
        pksplit(yacc[1][2], yacc[1][3], FH.w, FL.w);
        uint4* op = g_y + ((slice*4 + m)*2)*32 + lane;
        __stcg(op, FH);
        __stcg(op + 32, FL);
    }
    __syncthreads();

    // flag-group base: group mh uses flags [mh*64, mh*64+64)
    unsigned e = 0;
    gbar(cta, mh*64, tid, ++e);

    for (int t = 0; t < SEQ; t++){
        do_layer<0>(slice, m, lm, kq, lane, g_y,  g_wy,  g_hA, sbias[0], sred, yacc, out, t);
        gbar(cta, mh*64, tid, ++e);
        do_layer<1>(slice, m, lm, kq, lane, g_hA, g_wh0, g_hB, sbias[1], sred, yacc, out, t);
        gbar(cta, mh*64, tid, ++e);
        do_layer<1>(slice, m, lm, kq, lane, g_hB, g_wh1, g_hA, sbias[2], sred, yacc, out, t);
        gbar(cta, mh*64, tid, ++e);
        do_layer<2>(slice, m, lm, kq, lane, g_hA, g_wo,  g_y,  sbias[3], sred, yacc, out, t);
        gbar(cta, mh*64, tid, ++e);
    }
}

extern "C" void kernel_launch(void* const* d_in, const int* in_sizes, int n_in,
                              void* d_out, int out_size){
    const int*   x   = (const int*)  d_in[0];
    const float* emb = (const float*)d_in[1];
    const float* wy  = (const float*)d_in[2];
    const float* wx  = (const float*)d_in[3];
    const float* bin = (const float*)d_in[4];
    const float* wh  = (const float*)d_in[5];
    const float* bh  = (const float*)d_in[6];
    const float* wo  = (const float*)d_in[7];
    const float* bo  = (const float*)d_in[8];
    const float* h0  = (const float*)d_in[9];
    float* out = (float*)d_out;

    cudaFuncSetAttribute(hw_projx, cudaFuncAttributeMaxDynamicSharedMemorySize, 131072);

    hw_split<<<2304, 256>>>(wy, wx, wh, wo);
    hw_projx<<<4096, 256, 131072>>>(x, emb);
    hw_main<<<NCTA, 512>>>(bin, bh, bo, h0, out);
}